// round 16
// baseline (speedup 1.0000x reference)
#include <cuda_runtime.h>
#include <cuda_fp16.h>
#include <cstdint>

#define B_ 16
#define N_ 512
#define D_ 64
#define K_ 8

// ---------------- static device scratch -----------------------------------
__device__ __align__(16) __half   g_hT16[B_ * D_ * N_];        // [b][e][j] 1 MB
__device__ __align__(16) uint32_t g_Wf[2][K_][4][32][16];      // frag-packed W, 128 KB

// pitches
#define HT_PITCH   520   // halves; 1040 B rows: LDSM rows + LDS.32 tile all banks
#define SRED_PITCH 66    // floats per partial row (128 rows per ig-half)

// smem byte layout (sred overlays the ADJ buffer between dirs; hts persists)
#define OFF_HT   0
#define SZ_HT    (D_ * HT_PITCH * 2)             // 66560
#define OFF_ADJ  67584
#define SZ_ADJ   (128 * SRED_PITCH * 4)          // 33792 >= 32*HT_PITCH*2 = 33280
#define SB_SMEM  (OFF_ADJ + SZ_ADJ)              // 101376 -> 2 CTAs/SM

// ---------------- mma.sync m16n8k16 f16->f32 -------------------------------
__device__ __forceinline__ void mma16816(float* d,
                                         uint32_t a0, uint32_t a1, uint32_t a2, uint32_t a3,
                                         uint32_t b0, uint32_t b1) {
    asm volatile(
        "mma.sync.aligned.m16n8k16.row.col.f32.f16.f16.f32 "
        "{%0,%1,%2,%3}, {%4,%5,%6,%7}, {%8,%9}, {%0,%1,%2,%3};"
        : "+f"(d[0]), "+f"(d[1]), "+f"(d[2]), "+f"(d[3])
        : "r"(a0), "r"(a1), "r"(a2), "r"(a3), "r"(b0), "r"(b1));
}

__device__ __forceinline__ void ldsm_x4(uint32_t& r0, uint32_t& r1,
                                        uint32_t& r2, uint32_t& r3, uint32_t addr) {
    asm volatile("ldmatrix.sync.aligned.m8n8.x4.shared.b16 {%0,%1,%2,%3}, [%4];"
                 : "=r"(r0), "=r"(r1), "=r"(r2), "=r"(r3) : "r"(addr));
}

__device__ __forceinline__ uint32_t smem_u32(const void* p) {
    uint32_t a;
    asm("{ .reg .u64 t; cvta.to.shared.u64 t, %1; cvt.u32.u64 %0, t; }" : "=r"(a) : "l"(p));
    return a;
}

__device__ __forceinline__ uint32_t packh2(float x, float y) {
    __half2 h = __floats2half2_rn(x, y);
    return *reinterpret_cast<uint32_t*>(&h);
}

// one-hot fragment: fp16 1.0 where v==k (HSET2, one instruction)
__device__ __forceinline__ uint32_t heq_frag(uint32_t v, uint32_t k2) {
    __half2 r = __heq2(*reinterpret_cast<const __half2*>(&v),
                       *reinterpret_cast<const __half2*>(&k2));
    return *reinterpret_cast<uint32_t*>(&r);
}

// ---------------- kernel 1: prep (hT fp16 transpose + W frag pack) ---------
__global__ void prep(const float* __restrict__ h,
                     const float* __restrict__ min_, const float* __restrict__ mout_) {
    int bid = blockIdx.x;
    int tx = threadIdx.x, ty = threadIdx.y;        // 32 x 8
    if (bid < 512) {
        __shared__ float tile[32][33];
        int j0 = (bid & 15) * 32;
        int e0 = ((bid >> 4) & 1) * 32;
        int b  = bid >> 5;
#pragma unroll
        for (int r = 0; r < 32; r += 8)
            tile[ty + r][tx] = h[((size_t)b * N_ + j0 + ty + r) * D_ + e0 + tx];
        __syncthreads();
#pragma unroll
        for (int r = 0; r < 32; r += 8)
            g_hT16[((size_t)b * D_ + e0 + ty + r) * N_ + j0 + tx] =
                __float2half_rn(tile[tx][ty + r]);
    } else {
        int idx  = (bid - 512) * 256 + ty * 32 + tx;   // 0..32767
        int q    = idx & 1;
        int ng   = (idx >> 1) & 7;
        int lane = (idx >> 4) & 31;
        int dc   = (idx >> 9) & 3;
        int k    = (idx >> 11) & 7;
        int dir  = (idx >> 14) & 1;
        int e = dc * 16 + (lane & 3) * 2 + q * 8;
        int n = ng * 8 + (lane >> 2);
        const float* src = (dir ? mout_ : min_) + ((size_t)(k * 64 + n)) * 64 + e;
        g_Wf[dir][k][dc][lane][ng * 2 + q] = packh2(src[0], src[1]);
    }
}

// ---------------- kernel 2: fused one-hot HMMA + weight GEMM ---------------
// CTA = (b, 32-row i tile); processes BOTH directions with hT staged once.
// Warp w = (kp = w&3 -> k {2kp+1,2kp+2}, eh = w>>2).
__global__ __launch_bounds__(256, 2)
void fused(const int* __restrict__ adj, const float* __restrict__ bias,
           float* __restrict__ out) {
    extern __shared__ char sm[];
    __half* hts  = reinterpret_cast<__half*>(sm + OFF_HT);
    __half* hadj = reinterpret_cast<__half*>(sm + OFF_ADJ);
    float*  sred = reinterpret_cast<float*>(sm + OFF_ADJ);  // overlays adj between dirs

    int tid = threadIdx.x, lane = tid & 31, w = tid >> 5;
    int job   = blockIdx.x;          // 0..255
    int itile = job & 15;
    int b     = job >> 4;
    int i0    = itile * 32;
    int kp    = w & 3;               // k pair: {2kp+1, 2kp+2}
    int eh    = w >> 2;              // e half: cols [eh*32, eh*32+32)
    int t2    = (lane & 3) * 2;
    int g     = lane >> 2;

    uint32_t kk[2];
#pragma unroll
    for (int kl = 0; kl < 2; kl++) {
        __half kh = __int2half_rn(kp * 2 + kl + 1);
        __half2 k2 = __halves2half2(kh, kh);
        kk[kl] = *reinterpret_cast<uint32_t*>(&k2);
    }

    const int* adjb = adj + (size_t)b * N_ * N_;

    // ---- cooperative load: hT (64KB fp16) into smem, ONCE for both dirs ----
    {
        const uint4* src = reinterpret_cast<const uint4*>(g_hT16 + (size_t)b * D_ * N_);
#pragma unroll
        for (int s = 0; s < 16; s++) {
            int gg = tid + s * 256;               // 4096 uint4
            int e = gg >> 6, c = gg & 63;
            *reinterpret_cast<uint4*>(reinterpret_cast<char*>(hts)
                                      + e * (HT_PITCH * 2) + c * 16) = src[gg];
        }
    }

    uint32_t lm_base = smem_u32(hts)
                     + (eh * 32 + (lane & 7) + ((lane >> 4) & 1) * 8) * (HT_PITCH * 2)
                     + ((lane >> 3) & 1) * 16;
    const uint32_t* aj32 = reinterpret_cast<const uint32_t*>(hadj);

    for (int dir = 0; dir < 2; dir++) {
        // ---- stage adj tile (32 i x 512 j) as fp16 -------------------------
        if (dir == 0) {
            int row = tid >> 3;                 // 32 rows, 8 threads each
            int jb  = (tid & 7) * 64;           // 64 j per thread
            __half* drow = hadj + row * HT_PITCH;
#pragma unroll
            for (int u = 0; u < 4; u++) {
                int j = jb + u * 16;
                const int4* s = reinterpret_cast<const int4*>(&adjb[(size_t)(i0 + row) * N_ + j]);
                int4 q0 = s[0], q1 = s[1], q2 = s[2], q3 = s[3];
                __half2* d2 = reinterpret_cast<__half2*>(drow + j);
                d2[0] = __halves2half2(__int2half_rn(q0.x), __int2half_rn(q0.y));
                d2[1] = __halves2half2(__int2half_rn(q0.z), __int2half_rn(q0.w));
                d2[2] = __halves2half2(__int2half_rn(q1.x), __int2half_rn(q1.y));
                d2[3] = __halves2half2(__int2half_rn(q1.z), __int2half_rn(q1.w));
                d2[4] = __halves2half2(__int2half_rn(q2.x), __int2half_rn(q2.y));
                d2[5] = __halves2half2(__int2half_rn(q2.z), __int2half_rn(q2.w));
                d2[6] = __halves2half2(__int2half_rn(q3.x), __int2half_rn(q3.y));
                d2[7] = __halves2half2(__int2half_rn(q3.z), __int2half_rn(q3.w));
            }
        } else {
            // transposed: hadj[i][j] = adj[j][i0+i]
            int ib = (tid & 7) * 4;
#pragma unroll
            for (int it = 0; it < 16; it++) {
                int j = it * 32 + (tid >> 3);
                int4 v = *reinterpret_cast<const int4*>(&adjb[(size_t)j * N_ + i0 + ib]);
                hadj[(ib + 0) * HT_PITCH + j] = __int2half_rn(v.x);
                hadj[(ib + 1) * HT_PITCH + j] = __int2half_rn(v.y);
                hadj[(ib + 2) * HT_PITCH + j] = __int2half_rn(v.z);
                hadj[(ib + 3) * HT_PITCH + j] = __int2half_rn(v.w);
            }
        }
        __syncthreads();

        float acc[2][2][4][4];    // [kl][ig][nq][4]
#pragma unroll
        for (int kl = 0; kl < 2; kl++)
#pragma unroll
            for (int ig = 0; ig < 2; ig++)
#pragma unroll
                for (int nq = 0; nq < 4; nq++)
#pragma unroll
                    for (int q = 0; q < 4; q++) acc[kl][ig][nq][q] = 0.f;

        // ---- main loop: 32 js of 16 j, NO barriers -------------------------
#pragma unroll 4
        for (int js = 0; js < 32; js++) {
            uint32_t bb[4][2];
#pragma unroll
            for (int p = 0; p < 2; p++) {
                uint32_t addr = lm_base + p * (16 * HT_PITCH * 2) + js * 32;
                ldsm_x4(bb[2 * p][0], bb[2 * p][1], bb[2 * p + 1][0], bb[2 * p + 1][1], addr);
            }
#pragma unroll
            for (int ig = 0; ig < 2; ig++) {
                int rw = (ig * 16 + g) * (HT_PITCH / 2) + js * 8 + (lane & 3);
                uint32_t v00 = aj32[rw];
                uint32_t v01 = aj32[rw + 4];
                uint32_t v10 = aj32[rw + 8 * (HT_PITCH / 2)];
                uint32_t v11 = aj32[rw + 8 * (HT_PITCH / 2) + 4];
#pragma unroll
                for (int kl = 0; kl < 2; kl++) {
                    uint32_t a0 = heq_frag(v00, kk[kl]);
                    uint32_t a1 = heq_frag(v10, kk[kl]);
                    uint32_t a2 = heq_frag(v01, kk[kl]);
                    uint32_t a3 = heq_frag(v11, kk[kl]);
#pragma unroll
                    for (int nq = 0; nq < 4; nq++)
                        mma16816(acc[kl][ig][nq], a0, a1, a2, a3, bb[nq][0], bb[nq][1]);
                }
            }
        }

        // ---- pack acc -> fp16 A-fragments (registers only) ------------------
        uint32_t ah[2][2][2][4];   // [kl][ig][dcl][4]
#pragma unroll
        for (int kl = 0; kl < 2; kl++)
#pragma unroll
            for (int ig = 0; ig < 2; ig++)
#pragma unroll
                for (int dcl = 0; dcl < 2; dcl++) {
                    const float* cA = acc[kl][ig][2 * dcl];
                    const float* cB = acc[kl][ig][2 * dcl + 1];
                    ah[kl][ig][dcl][0] = packh2(cA[0], cA[1]);
                    ah[kl][ig][dcl][1] = packh2(cA[2], cA[3]);
                    ah[kl][ig][dcl][2] = packh2(cB[0], cB[1]);
                    ah[kl][ig][dcl][3] = packh2(cB[2], cB[3]);
                }

        // ---- epilogue P[i][n] = sum_e S[i][e] * W[k][n][e] ------------------
        float oacc[2][8][4];
#pragma unroll
        for (int ig = 0; ig < 2; ig++)
#pragma unroll
            for (int ng = 0; ng < 8; ng++)
#pragma unroll
                for (int q = 0; q < 4; q++) oacc[ig][ng][q] = 0.f;

#pragma unroll
        for (int kl = 0; kl < 2; kl++) {
            int k = kp * 2 + kl;
#pragma unroll
            for (int dcl = 0; dcl < 2; dcl++) {
                int dcg = eh * 2 + dcl;
                const uint4* wk = reinterpret_cast<const uint4*>(&g_Wf[dir][k][dcg][lane][0]);
                uint4 w0 = wk[0], w1 = wk[1], w2 = wk[2], w3 = wk[3];
                uint32_t wb[8][2] = {
                    {w0.x, w0.y}, {w0.z, w0.w}, {w1.x, w1.y}, {w1.z, w1.w},
                    {w2.x, w2.y}, {w2.z, w2.w}, {w3.x, w3.y}, {w3.z, w3.w}};
#pragma unroll
                for (int ng = 0; ng < 8; ng++) {
                    mma16816(oacc[0][ng], ah[kl][0][dcl][0], ah[kl][0][dcl][1],
                             ah[kl][0][dcl][2], ah[kl][0][dcl][3], wb[ng][0], wb[ng][1]);
                    mma16816(oacc[1][ng], ah[kl][1][dcl][0], ah[kl][1][dcl][1],
                             ah[kl][1][dcl][2], ah[kl][1][dcl][3], wb[ng][0], wb[ng][1]);
                }
            }
        }
        __syncthreads();   // all warps done reading hadj -> safe to overlay sred

        // ---- reduction in two ig-halves (sred overlays adj buffer) ----------
#pragma unroll
        for (int ig = 0; ig < 2; ig++) {
            // store partials: 8 warps x 16 rows = 128 rows, pitch 66
            float* sr = sred + (size_t)(w * 16) * SRED_PITCH;
#pragma unroll
            for (int ng = 0; ng < 8; ng++) {
                float2 lo = make_float2(oacc[ig][ng][0], oacc[ig][ng][1]);
                float2 hi = make_float2(oacc[ig][ng][2], oacc[ig][ng][3]);
                *reinterpret_cast<float2*>(&sr[g * SRED_PITCH + ng * 8 + t2])       = lo;
                *reinterpret_cast<float2*>(&sr[(g + 8) * SRED_PITCH + ng * 8 + t2]) = hi;
            }
            __syncthreads();

            // final sum over 8 k-partials + bias + store (16 rows x 64 cols)
            {
                int r  = tid >> 4;            // 0..15 (i row within half)
                int nb = (tid & 15) * 4;      // 0..60 (n col base)
                float s[4] = {0.f, 0.f, 0.f, 0.f};
#pragma unroll
                for (int ww = 0; ww < 8; ww++) {
                    const float* p = sred + (size_t)(ww * 16 + r) * SRED_PITCH + nb;
                    float2 u0 = *reinterpret_cast<const float2*>(p);
                    float2 u1 = *reinterpret_cast<const float2*>(p + 2);
                    s[0] += u0.x; s[1] += u0.y; s[2] += u1.x; s[3] += u1.y;
                }
                const float* bp = bias + dir * 64 + nb;
                float4 o;
                o.x = s[0] + bp[0]; o.y = s[1] + bp[1];
                o.z = s[2] + bp[2]; o.w = s[3] + bp[3];
                *reinterpret_cast<float4*>(
                    &out[(size_t)((b * N_) + i0 + ig * 16 + r) * 128 + dir * 64 + nb]) = o;
            }
            __syncthreads();
        }
        // last __syncthreads above also protects hadj re-staging for dir=1
    }
}

// ---------------- launch ----------------------------------------------------
extern "C" void kernel_launch(void* const* d_in, const int* in_sizes, int n_in,
                              void* d_out, int out_size) {
    const float* h     = (const float*)d_in[0];   // [16,512,64]
    const int*   adj   = (const int*)d_in[1];     // [16,512,512]
    const float* min_  = (const float*)d_in[3];   // [8,64,64]
    const float* mout_ = (const float*)d_in[4];   // [8,64,64]
    const float* bias  = (const float*)d_in[5];   // [128]
    float* out = (float*)d_out;                   // [16,512,128]

    static int cfg = 0;
    if (!cfg) {
        cudaFuncSetAttribute(fused, cudaFuncAttributeMaxDynamicSharedMemorySize, SB_SMEM);
        cfg = 1;
    }

    prep<<<640, dim3(32, 8)>>>(h, min_, mout_);
    fused<<<256, 256, SB_SMEM>>>(adj, bias, out);  // 16 b x 16 itiles, both dirs
}

// round 17
// speedup vs baseline: 1.1363x; 1.1363x over previous
#include <cuda_runtime.h>
#include <cuda_fp16.h>
#include <cstdint>

#define B_ 16
#define N_ 512
#define D_ 64
#define K_ 8

// ---------------- static device scratch -----------------------------------
__device__ __align__(16) __half   g_hT16[B_ * D_ * N_];        // [b][e][j] 1 MB
__device__ __align__(16) uint32_t g_Wf[2][K_][4][32][16];      // frag-packed W, 128 KB

// pitches (halves)
#define HT_PITCH   520   // 1040 B rows: LDSM rows + LDS.32 tile all banks
#define SRED_PITCH 66    // floats per i-row

// smem byte layout (sred overlays hT after the main loop)
#define OFF_HT   0
#define SZ_HT    (D_ * HT_PITCH * 2)             // 66560
#define OFF_ADJ  67584                           // = 256*66*4 (sred end)
#define SZ_ADJ   (32 * HT_PITCH * 2)             // 33280 (fp16 adj tile)
#define SB_SMEM  (OFF_ADJ + SZ_ADJ)              // 100864 -> 2 CTAs/SM

// ---------------- mma.sync m16n8k16 f16->f32 -------------------------------
__device__ __forceinline__ void mma16816(float* d,
                                         uint32_t a0, uint32_t a1, uint32_t a2, uint32_t a3,
                                         uint32_t b0, uint32_t b1) {
    asm volatile(
        "mma.sync.aligned.m16n8k16.row.col.f32.f16.f16.f32 "
        "{%0,%1,%2,%3}, {%4,%5,%6,%7}, {%8,%9}, {%0,%1,%2,%3};"
        : "+f"(d[0]), "+f"(d[1]), "+f"(d[2]), "+f"(d[3])
        : "r"(a0), "r"(a1), "r"(a2), "r"(a3), "r"(b0), "r"(b1));
}

__device__ __forceinline__ void ldsm_x4(uint32_t& r0, uint32_t& r1,
                                        uint32_t& r2, uint32_t& r3, uint32_t addr) {
    asm volatile("ldmatrix.sync.aligned.m8n8.x4.shared.b16 {%0,%1,%2,%3}, [%4];"
                 : "=r"(r0), "=r"(r1), "=r"(r2), "=r"(r3) : "r"(addr));
}

__device__ __forceinline__ uint32_t smem_u32(const void* p) {
    uint32_t a;
    asm("{ .reg .u64 t; cvta.to.shared.u64 t, %1; cvt.u32.u64 %0, t; }" : "=r"(a) : "l"(p));
    return a;
}

__device__ __forceinline__ uint32_t packh2(float x, float y) {
    __half2 h = __floats2half2_rn(x, y);
    return *reinterpret_cast<uint32_t*>(&h);
}

// one-hot fragment: fp16 1.0 where v==k (HSET2, one instruction)
__device__ __forceinline__ uint32_t heq_frag(uint32_t v, uint32_t k2) {
    __half2 r = __heq2(*reinterpret_cast<const __half2*>(&v),
                       *reinterpret_cast<const __half2*>(&k2));
    return *reinterpret_cast<uint32_t*>(&r);
}

// ---------------- kernel 1: prep (hT fp16 transpose + W frag pack) ---------
__global__ void prep(const float* __restrict__ h,
                     const float* __restrict__ min_, const float* __restrict__ mout_) {
    int bid = blockIdx.x;
    int tx = threadIdx.x, ty = threadIdx.y;        // 32 x 8
    if (bid < 512) {
        __shared__ float tile[32][33];
        int j0 = (bid & 15) * 32;
        int e0 = ((bid >> 4) & 1) * 32;
        int b  = bid >> 5;
#pragma unroll
        for (int r = 0; r < 32; r += 8)
            tile[ty + r][tx] = h[((size_t)b * N_ + j0 + ty + r) * D_ + e0 + tx];
        __syncthreads();
#pragma unroll
        for (int r = 0; r < 32; r += 8)
            g_hT16[((size_t)b * D_ + e0 + ty + r) * N_ + j0 + tx] =
                __float2half_rn(tile[tx][ty + r]);
    } else {
        int idx  = (bid - 512) * 256 + ty * 32 + tx;   // 0..32767
        int q    = idx & 1;
        int ng   = (idx >> 1) & 7;
        int lane = (idx >> 4) & 31;
        int dc   = (idx >> 9) & 3;
        int k    = (idx >> 11) & 7;
        int dir  = (idx >> 14) & 1;
        int e = dc * 16 + (lane & 3) * 2 + q * 8;
        int n = ng * 8 + (lane >> 2);
        const float* src = (dir ? mout_ : min_) + ((size_t)(k * 64 + n)) * 64 + e;
        g_Wf[dir][k][dc][lane][ng * 2 + q] = packh2(src[0], src[1]);
    }
}

// ---------------- kernel 2: fused one-hot HMMA + weight GEMM ---------------
// CTA = (dir, b, 32-row i tile). Warp w = (kp = w&3 -> k {2kp+1,2kp+2}, eh = w>>2).
__global__ __launch_bounds__(256, 2)
void fused(const int* __restrict__ adj, const float* __restrict__ bias,
           float* __restrict__ out) {
    extern __shared__ char sm[];
    __half* hts  = reinterpret_cast<__half*>(sm + OFF_HT);
    __half* hadj = reinterpret_cast<__half*>(sm + OFF_ADJ);
    float*  sred = reinterpret_cast<float*>(sm + OFF_HT);   // reuse after mainloop

    int tid = threadIdx.x, lane = tid & 31, w = tid >> 5;
    int job   = blockIdx.x;
    int itile = job & 15;
    int b     = (job >> 4) & 15;
    int dir   = job >> 8;
    int i0    = itile * 32;
    int kp    = w & 3;              // k pair: {2kp+1, 2kp+2}
    int eh    = w >> 2;             // e half: cols [eh*32, eh*32+32)
    int t2    = (lane & 3) * 2;
    int g     = lane >> 2;

    // packed half2 constants for the two edge types
    uint32_t kk[2];
#pragma unroll
    for (int kl = 0; kl < 2; kl++) {
        __half kh = __int2half_rn(kp * 2 + kl + 1);
        __half2 k2 = __halves2half2(kh, kh);
        kk[kl] = *reinterpret_cast<uint32_t*>(&k2);
    }

    const int* adjb = adj + (size_t)b * N_ * N_;

    // ---- cooperative load: hT (64KB fp16) into smem ------------------------
    {
        const uint4* src = reinterpret_cast<const uint4*>(g_hT16 + (size_t)b * D_ * N_);
#pragma unroll
        for (int s = 0; s < 16; s++) {
            int gg = tid + s * 256;               // 4096 uint4
            int e = gg >> 6, c = gg & 63;
            *reinterpret_cast<uint4*>(reinterpret_cast<char*>(hts)
                                      + e * (HT_PITCH * 2) + c * 16) = src[gg];
        }
    }

    // ---- stage whole adj tile (32 i x 512 j) as fp16, once -----------------
    if (dir == 0) {
        int row = tid >> 3;                 // 32 rows, 8 threads each
        int jb  = (tid & 7) * 64;           // 64 j per thread
        __half* drow = hadj + row * HT_PITCH;
#pragma unroll
        for (int u = 0; u < 4; u++) {
            int j = jb + u * 16;
            const int4* s = reinterpret_cast<const int4*>(&adjb[(size_t)(i0 + row) * N_ + j]);
            int4 q0 = s[0], q1 = s[1], q2 = s[2], q3 = s[3];
            __half2* d2 = reinterpret_cast<__half2*>(drow + j);
            d2[0] = __halves2half2(__int2half_rn(q0.x), __int2half_rn(q0.y));
            d2[1] = __halves2half2(__int2half_rn(q0.z), __int2half_rn(q0.w));
            d2[2] = __halves2half2(__int2half_rn(q1.x), __int2half_rn(q1.y));
            d2[3] = __halves2half2(__int2half_rn(q1.z), __int2half_rn(q1.w));
            d2[4] = __halves2half2(__int2half_rn(q2.x), __int2half_rn(q2.y));
            d2[5] = __halves2half2(__int2half_rn(q2.z), __int2half_rn(q2.w));
            d2[6] = __halves2half2(__int2half_rn(q3.x), __int2half_rn(q3.y));
            d2[7] = __halves2half2(__int2half_rn(q3.z), __int2half_rn(q3.w));
        }
    } else {
        // transposed: hadj[i][j] = adj[j][i0+i]
        int ib = (tid & 7) * 4;
#pragma unroll
        for (int it = 0; it < 16; it++) {
            int j = it * 32 + (tid >> 3);
            int4 v = *reinterpret_cast<const int4*>(&adjb[(size_t)j * N_ + i0 + ib]);
            hadj[(ib + 0) * HT_PITCH + j] = __int2half_rn(v.x);
            hadj[(ib + 1) * HT_PITCH + j] = __int2half_rn(v.y);
            hadj[(ib + 2) * HT_PITCH + j] = __int2half_rn(v.z);
            hadj[(ib + 3) * HT_PITCH + j] = __int2half_rn(v.w);
        }
    }
    __syncthreads();

    uint32_t lm_base = smem_u32(hts)
                     + (eh * 32 + (lane & 7) + ((lane >> 4) & 1) * 8) * (HT_PITCH * 2)
                     + ((lane >> 3) & 1) * 16;
    const uint32_t* aj32 = reinterpret_cast<const uint32_t*>(hadj);

    float acc[2][2][4][4];    // [kl][ig][nq][4]
#pragma unroll
    for (int kl = 0; kl < 2; kl++)
#pragma unroll
        for (int ig = 0; ig < 2; ig++)
#pragma unroll
            for (int nq = 0; nq < 4; nq++)
#pragma unroll
                for (int q = 0; q < 4; q++) acc[kl][ig][nq][q] = 0.f;

    // ---- main loop: 32 js of 16 j, NO barriers -----------------------------
#pragma unroll 4
    for (int js = 0; js < 32; js++) {
        uint32_t bb[4][2];
#pragma unroll
        for (int p = 0; p < 2; p++) {
            uint32_t addr = lm_base + p * (16 * HT_PITCH * 2) + js * 32;
            ldsm_x4(bb[2 * p][0], bb[2 * p][1], bb[2 * p + 1][0], bb[2 * p + 1][1], addr);
        }
#pragma unroll
        for (int ig = 0; ig < 2; ig++) {
            int rw = (ig * 16 + g) * (HT_PITCH / 2) + js * 8 + (lane & 3);
            uint32_t v00 = aj32[rw];
            uint32_t v01 = aj32[rw + 4];
            uint32_t v10 = aj32[rw + 8 * (HT_PITCH / 2)];
            uint32_t v11 = aj32[rw + 8 * (HT_PITCH / 2) + 4];
#pragma unroll
            for (int kl = 0; kl < 2; kl++) {
                uint32_t a0 = heq_frag(v00, kk[kl]);
                uint32_t a1 = heq_frag(v10, kk[kl]);
                uint32_t a2 = heq_frag(v01, kk[kl]);
                uint32_t a3 = heq_frag(v11, kk[kl]);
#pragma unroll
                for (int nq = 0; nq < 4; nq++)
                    mma16816(acc[kl][ig][nq], a0, a1, a2, a3, bb[nq][0], bb[nq][1]);
            }
        }
    }
    __syncthreads();   // protect hts region before sred overlay

    // ---- phase 1: pack acc -> fp16 A-fragments (acc dies) ------------------
    uint32_t ah[2][2][2][4];   // [kl][ig][dcl][4]
#pragma unroll
    for (int kl = 0; kl < 2; kl++)
#pragma unroll
        for (int ig = 0; ig < 2; ig++)
#pragma unroll
            for (int dcl = 0; dcl < 2; dcl++) {
                const float* cA = acc[kl][ig][2 * dcl];
                const float* cB = acc[kl][ig][2 * dcl + 1];
                ah[kl][ig][dcl][0] = packh2(cA[0], cA[1]);
                ah[kl][ig][dcl][1] = packh2(cA[2], cA[3]);
                ah[kl][ig][dcl][2] = packh2(cB[0], cB[1]);
                ah[kl][ig][dcl][3] = packh2(cB[2], cB[3]);
            }

    // ---- phase 2: epilogue P[i][n] = sum_e S[i][e] * W[k][n][e] ------------
    float oacc[2][8][4];
#pragma unroll
    for (int ig = 0; ig < 2; ig++)
#pragma unroll
        for (int ng = 0; ng < 8; ng++)
#pragma unroll
            for (int q = 0; q < 4; q++) oacc[ig][ng][q] = 0.f;

#pragma unroll
    for (int kl = 0; kl < 2; kl++) {
        int k = kp * 2 + kl;
#pragma unroll
        for (int dcl = 0; dcl < 2; dcl++) {
            int dcg = eh * 2 + dcl;
            const uint4* wk = reinterpret_cast<const uint4*>(&g_Wf[dir][k][dcg][lane][0]);
            uint4 w0 = wk[0], w1 = wk[1], w2 = wk[2], w3 = wk[3];
            uint32_t wb[8][2] = {
                {w0.x, w0.y}, {w0.z, w0.w}, {w1.x, w1.y}, {w1.z, w1.w},
                {w2.x, w2.y}, {w2.z, w2.w}, {w3.x, w3.y}, {w3.z, w3.w}};
#pragma unroll
            for (int ng = 0; ng < 8; ng++) {
                mma16816(oacc[0][ng], ah[kl][0][dcl][0], ah[kl][0][dcl][1],
                         ah[kl][0][dcl][2], ah[kl][0][dcl][3], wb[ng][0], wb[ng][1]);
                mma16816(oacc[1][ng], ah[kl][1][dcl][0], ah[kl][1][dcl][1],
                         ah[kl][1][dcl][2], ah[kl][1][dcl][3], wb[ng][0], wb[ng][1]);
            }
        }
    }

    // ---- per-warp partials into smem ----------------------------------------
    float* sr = sred + (size_t)w * 32 * SRED_PITCH;
#pragma unroll
    for (int ig = 0; ig < 2; ig++)
#pragma unroll
        for (int ng = 0; ng < 8; ng++) {
            float2 lo = make_float2(oacc[ig][ng][0], oacc[ig][ng][1]);
            float2 hi = make_float2(oacc[ig][ng][2], oacc[ig][ng][3]);
            *reinterpret_cast<float2*>(&sr[(ig * 16 + g) * SRED_PITCH + ng * 8 + t2])     = lo;
            *reinterpret_cast<float2*>(&sr[(ig * 16 + g + 8) * SRED_PITCH + ng * 8 + t2]) = hi;
        }
    __syncthreads();

    // ---- final sum over 8 partials + bias + store ---------------------------
    {
        int r  = tid >> 3;            // 0..31 (i row)
        int nb = (tid & 7) * 8;       // 0..56 (n col base)
        float s[8];
#pragma unroll
        for (int u = 0; u < 8; u++) s[u] = 0.f;
#pragma unroll
        for (int ww = 0; ww < 8; ww++) {
            const float* p = sred + (size_t)(ww * 32 + r) * SRED_PITCH + nb;
#pragma unroll
            for (int u = 0; u < 8; u++) s[u] += p[u];
        }
        const float* bp = bias + dir * 64 + nb;
        float* op = &out[(size_t)((b * N_) + i0 + r) * 128 + dir * 64 + nb];
        float4 o0, o1;
        o0.x = s[0] + bp[0]; o0.y = s[1] + bp[1]; o0.z = s[2] + bp[2]; o0.w = s[3] + bp[3];
        o1.x = s[4] + bp[4]; o1.y = s[5] + bp[5]; o1.z = s[6] + bp[6]; o1.w = s[7] + bp[7];
        *reinterpret_cast<float4*>(op)     = o0;
        *reinterpret_cast<float4*>(op + 4) = o1;
    }
}

// ---------------- launch ----------------------------------------------------
extern "C" void kernel_launch(void* const* d_in, const int* in_sizes, int n_in,
                              void* d_out, int out_size) {
    const float* h     = (const float*)d_in[0];   // [16,512,64]
    const int*   adj   = (const int*)d_in[1];     // [16,512,512]
    const float* min_  = (const float*)d_in[3];   // [8,64,64]
    const float* mout_ = (const float*)d_in[4];   // [8,64,64]
    const float* bias  = (const float*)d_in[5];   // [128]
    float* out = (float*)d_out;                   // [16,512,128]

    static int cfg = 0;
    if (!cfg) {
        cudaFuncSetAttribute(fused, cudaFuncAttributeMaxDynamicSharedMemorySize, SB_SMEM);
        cfg = 1;
    }

    prep<<<640, dim3(32, 8)>>>(h, min_, mout_);
    fused<<<512, 256, SB_SMEM>>>(adj, bias, out);  // 2 dir x 16 b x 16 itiles
}